// round 16
// baseline (speedup 1.0000x reference)
#include <cuda_runtime.h>
#include <cuda_bf16.h>
#include <cstdint>

#define NN 100000      // nodes
#define RR 6           // relations
#define EE 400000      // edges per relation
#define FD 128         // feature dim
#define RE (RR * EE)   // 2.4M edges
#define RN (RR * NN)   // 600k
#define NPART ((RN + 255) / 256)   // 2344 scan partials

// ---------------- scratch (device globals, ~85 MB) ---------------------------
__device__ int   g_dego[RN];
__device__ int   g_degi[RN];
__device__ float g_ns[RN];
__device__ float g_nd[RN];
__device__ int   g_off[RN + 1];           // CSR offsets over (r,node)
__device__ int   g_cur[RN];
__device__ int   g_part[NPART];
__device__ int   g_bsrc[RE];              // binned edge src
__device__ float g_bcoef[RE];             // binned edge coef
__device__ float g_w[RN];                 // per-(r,src) coef sums (layer-2)
__device__ float g_H1 [(size_t)NN * FD];
__device__ float g_s2 [RR * FD];
__device__ int   g_cnt[4];

// role pointers decided on-device
__device__ const float* g_x;
__device__ const int*   g_es;
__device__ const int*   g_ed;
__device__ const float* g_W1;
__device__ const float* g_W2;
__device__ const float* g_b1;
__device__ const float* g_b2;
__device__ const float* g_Wc;
__device__ const float* g_bc;
__device__ int g_e64;
__device__ int g_diagcode;

// ---------------- eager module load (KEEP: fixed R6) --------------------------
namespace {
struct EagerModuleLoad {
    EagerModuleLoad() {
        void* p = nullptr;
        cudaGetSymbolAddress(&p, g_H1);
        cudaGetSymbolAddress(&p, g_bsrc);
        cudaDeviceSynchronize();
    }
};
EagerModuleLoad g_eager_module_load;
}

// ---------------- content-based input classification (unchanged, works) ------
struct InArgs { const void* p[9]; long long sz[9]; };

__global__ void classify_kernel(InArgs a) {
    if (threadIdx.x || blockIdx.x) return;
    int cls[9];
    for (int i = 0; i < 9; i++) {
        const unsigned* u = (const unsigned*)a.p[i];
        unsigned u0 = u[0], u1 = u[1];
        if (u0 == 0u && u1 == 0u) cls[i] = 0;
        else if (u0 < 131072u && u1 < 131072u) cls[i] = 1;
        else cls[i] = 2;
    }
    int nb = 0, ne = 0, nf = 0;
    for (int i = 0; i < 9; i++) { nb += cls[i] == 0; ne += cls[i] == 1; nf += cls[i] == 2; }

    int diag = 0;
    int ix = -1, ie0 = -1, ie1 = -1, iW1 = -1, iW2 = -1, iWc = -1, ib1 = -1, ib2 = -1, ibc = -1;
    if (nb == 3 && ne == 2 && nf == 4) {
        long long best = -1;
        for (int i = 0; i < 9; i++) if (cls[i] == 2 && a.sz[i] > best) { best = a.sz[i]; ix = i; }
        best = 0x7fffffffffffffffLL;
        for (int i = 0; i < 9; i++) if (cls[i] == 2 && i != ix && a.sz[i] < best) { best = a.sz[i]; iWc = i; }
        for (int i = 0; i < 9; i++) if (cls[i] == 2 && i != ix && i != iWc) { if (iW1 < 0) iW1 = i; else iW2 = i; }
        best = 0x7fffffffffffffffLL;
        for (int i = 0; i < 9; i++) if (cls[i] == 0 && a.sz[i] < best) { best = a.sz[i]; ibc = i; }
        for (int i = 0; i < 9; i++) if (cls[i] == 0 && i != ibc) { if (ib1 < 0) ib1 = i; else ib2 = i; }
        for (int i = 0; i < 9; i++) if (cls[i] == 1) { if (ie0 < 0) ie0 = i; else ie1 = i; }
    } else {
        diag = 1;
        ix = 0; ie0 = 1; ie1 = 2; iW1 = 3; ib1 = 4; iW2 = 5; ib2 = 6; iWc = 7; ibc = 8;
    }
    int isrc = ie0, idst = ie1;
    if (ix > ie0) { isrc = ie1; idst = ie0; }

    g_x  = (const float*)a.p[ix];
    g_es = (const int*)  a.p[isrc];
    g_ed = (const int*)  a.p[idst];
    g_W1 = (const float*)a.p[iW1];
    g_W2 = (const float*)a.p[iW2];
    g_b1 = (const float*)a.p[ib1];
    g_b2 = (const float*)a.p[ib2];
    g_Wc = (const float*)a.p[iWc];
    g_bc = (const float*)a.p[ibc];

    const unsigned* u = (const unsigned*)a.p[isrc];
    g_e64 = (u[1] == 0u && u[3] == 0u && u[5] == 0u && u[7] == 0u &&
             u[0] < NN && u[2] < NN && u[4] < NN && u[6] < NN) ? 1 : 0;
    g_diagcode = diag;
}

__device__ __forceinline__ int eload(const int* base, long long idx) {
    return g_e64 ? base[2 * idx] : base[idx];
}

// ---------------- zero -------------------------------------------------------
__global__ void zero_pre_kernel() {
    int i = blockIdx.x * blockDim.x + threadIdx.x;
    int stride = gridDim.x * blockDim.x;
    for (int k = i; k < RN; k += stride) {
        g_dego[k] = 0; g_degi[k] = 0; g_w[k] = 0.f;
    }
    if (i < RR * FD) g_s2[i] = 0.f;
    if (i < 4) g_cnt[i] = 0;
}

// ---------------- degree / norm ---------------------------------------------
__global__ void degree_kernel() {
    int gid = blockIdx.x * blockDim.x + threadIdx.x;
    if (gid >= RE) return;
    int r = gid / EE;
    unsigned s = (unsigned)eload(g_es, gid);
    unsigned d = (unsigned)eload(g_ed, gid);
    if (s < NN) atomicAdd(&g_dego[r * NN + s], 1);
    if (d < NN) atomicAdd(&g_degi[r * NN + d], 1);
}

__global__ void norm_kernel() {
    int i = blockIdx.x * blockDim.x + threadIdx.x;
    if (i >= RN) return;
    int dso = g_dego[i];
    int dsi = g_degi[i];
    if ((i & 1023) == 0 && (dso > 0 || dsi > 0)) atomicAdd(&g_cnt[0], 1);
    g_ns[i] = (dso > 0) ? rsqrtf((float)dso) : 0.f;
    g_nd[i] = (dsi > 0) ? rsqrtf((float)dsi) : 0.f;
}

// ---------------- exclusive scan of g_degi -> g_off, g_cur -------------------
__global__ void scan1_kernel() {
    __shared__ int sh[256];
    int i = blockIdx.x * 256 + threadIdx.x;
    sh[threadIdx.x] = (i < RN) ? g_degi[i] : 0;
    __syncthreads();
    for (int s = 128; s > 0; s >>= 1) {
        if (threadIdx.x < s) sh[threadIdx.x] += sh[threadIdx.x + s];
        __syncthreads();
    }
    if (threadIdx.x == 0) g_part[blockIdx.x] = sh[0];
}

__global__ void scan2_kernel() {
    __shared__ int sh[1024];
    int t = threadIdx.x;
    int c0 = t * 3;
    int vals[3];
    int loc = 0;
#pragma unroll
    for (int k = 0; k < 3; k++) {
        int idx = c0 + k;
        vals[k] = (idx < NPART) ? g_part[idx] : 0;
        loc += vals[k];
    }
    sh[t] = loc;
    __syncthreads();
    for (int off = 1; off < 1024; off <<= 1) {
        int v = (t >= off) ? sh[t - off] : 0;
        __syncthreads();
        sh[t] += v;
        __syncthreads();
    }
    int run = sh[t] - loc;
#pragma unroll
    for (int k = 0; k < 3; k++) {
        int idx = c0 + k;
        if (idx < NPART) { g_part[idx] = run; run += vals[k]; }
    }
}

__global__ void scan3_kernel() {
    __shared__ int sh[256];
    int t = threadIdx.x;
    int i = blockIdx.x * 256 + t;
    int v = (i < RN) ? g_degi[i] : 0;
    sh[t] = v;
    __syncthreads();
    for (int off = 1; off < 256; off <<= 1) {
        int u = (t >= off) ? sh[t - off] : 0;
        __syncthreads();
        sh[t] += u;
        __syncthreads();
    }
    int excl = sh[t] - v + g_part[blockIdx.x];
    if (i < RN) { g_off[i] = excl; g_cur[i] = excl; }
    if (i == RN - 1) g_off[RN] = excl + v;
}

// ---------------- bin edges into CSR + layer-2 weights -----------------------
__global__ void bin_kernel() {
    int gid = blockIdx.x * blockDim.x + threadIdx.x;
    if (gid >= RE) return;
    int r = gid / EE;
    unsigned s = (unsigned)eload(g_es, gid);
    unsigned d = (unsigned)eload(g_ed, gid);
    if (s >= NN || d >= NN) return;
    float c = g_ns[r * NN + s] * g_nd[r * NN + d];
    int pos = atomicAdd(&g_cur[r * NN + d], 1);
    g_bsrc[pos]  = (int)s;
    g_bcoef[pos] = c;
    atomicAdd(&g_w[r * NN + s], c);
    if ((gid & 4095) == 0 && c != 0.f) atomicAdd(&g_cnt[1], 1);
}

// ---------------- bf16 / mma / ldmatrix helpers -------------------------------
__device__ __forceinline__ unsigned pack_bf16(float lo, float hi) {
    unsigned r;
    asm("cvt.rn.bf16x2.f32 %0, %1, %2;" : "=r"(r) : "f"(hi), "f"(lo));
    return r;
}

__device__ __forceinline__ void mma_bf16(float& d0, float& d1, float& d2, float& d3,
                                         unsigned a0, unsigned a1, unsigned a2, unsigned a3,
                                         unsigned b0, unsigned b1) {
    asm volatile("mma.sync.aligned.m16n8k16.row.col.f32.bf16.bf16.f32 "
                 "{%0,%1,%2,%3}, {%4,%5,%6,%7}, {%8,%9}, {%0,%1,%2,%3};"
                 : "+f"(d0), "+f"(d1), "+f"(d2), "+f"(d3)
                 : "r"(a0), "r"(a1), "r"(a2), "r"(a3), "r"(b0), "r"(b1));
}

__device__ __forceinline__ void ldsm_x4(unsigned& r0, unsigned& r1,
                                        unsigned& r2, unsigned& r3, unsigned addr) {
    asm volatile("ldmatrix.sync.aligned.m8n8.x4.shared.b16 {%0,%1,%2,%3}, [%4];"
                 : "=r"(r0), "=r"(r1), "=r"(r2), "=r"(r3) : "r"(addr));
}

// ---------------- FUSED layer 1 (bf16 m16n8k16 + ldmatrix) --------------------
// Same tiles/layouts as the 587us version; the only change is the mainloop
// fragment loads: 24 scalar LDS/k-step -> 6 LDSM.x4/k-step.
#define SW16 68          // row stride in words (64 + 4 pad; LDSM rows cover all 32 banks)
__global__ __launch_bounds__(256)
void fused_l1_kernel() {
    __shared__ unsigned sA16[128][SW16];   // [m][k/2] bf16x2 (34.8 KB)
    __shared__ unsigned sB16[128][SW16];   // [n][k/2] bf16x2 (34.8 KB)
    __shared__ float sbias[FD];

    const int row0 = blockIdx.x * 128;
    const int tid  = threadIdx.x;
    const int wid  = tid >> 5;
    const int lane = tid & 31;
    const int gq   = lane >> 2;
    const int tq   = lane & 3;
    const int mbase = (wid & 1) * 64;
    const int nbase = (wid >> 1) * 32;

    if (tid < FD) {
        float bs = 0.f;
#pragma unroll
        for (int rr = 0; rr < RR; rr++) bs += g_b1[rr * FD + tid];
        sbias[tid] = bs;
    }

    // ldmatrix per-thread base addresses (byte addresses in shared space)
    // A (x4 -> a[mf][0..3]): groups t0-7:(m, k0) t8-15:(m+8, k0) t16-23:(m, k+4) t24-31:(m+8, k+4)
    const int arow  = mbase + (lane & 7) + ((lane >> 3) & 1) * 8;
    const int akoff = ((lane >> 4) & 1) * 4;
    unsigned aBase = (unsigned)__cvta_generic_to_shared(&sA16[arow][akoff]);
    // B (x4 -> b[nf][0],b[nf][1],b[nf+1][0],b[nf+1][1]):
    // groups t0-7:(n, k0) t8-15:(n, k+4) t16-23:(n+8, k0) t24-31:(n+8, k+4)
    const int brow  = nbase + (lane & 7) + ((lane >> 4) & 1) * 8;
    const int bkoff = ((lane >> 3) & 1) * 4;
    unsigned bBase = (unsigned)__cvta_generic_to_shared(&sB16[brow][bkoff]);
    const unsigned aMfStride = 16 * SW16 * 4;   // 16 rows per mf
    const unsigned bPairStride = 16 * SW16 * 4; // nf pair 2..3 is +16 rows

    float acc[4][4][4];
#pragma unroll
    for (int mf = 0; mf < 4; mf++)
#pragma unroll
        for (int nf = 0; nf < 4; nf++)
#pragma unroll
            for (int q = 0; q < 4; q++) acc[mf][nf][q] = 0.f;

    for (int r = 0; r < RR; r++) {
        const float* Wr = g_W1 + (size_t)r * FD * FD;
        __syncthreads();   // previous relation's mma done reading sA16/sB16

        // ---- full-K gather: warp w covers nodes w*16..w*16+15; lane owns 4 cols
#pragma unroll 1
        for (int i = 0; i < 16; i++) {
            int m  = wid * 16 + i;
            int gn = row0 + m;
            float4 a4 = make_float4(0.f, 0.f, 0.f, 0.f);
            if (gn < NN) {
                int base = r * NN + gn;
                int e  = g_off[base];
                int e1 = g_off[base + 1];
                const float* xk = g_x + lane * 4;
                for (; e + 1 < e1; e += 2) {
                    int   s0 = g_bsrc[e],  s1 = g_bsrc[e + 1];
                    float c0 = g_bcoef[e], c1 = g_bcoef[e + 1];
                    float4 v0 = *(const float4*)(xk + (size_t)s0 * FD);
                    float4 v1 = *(const float4*)(xk + (size_t)s1 * FD);
                    a4.x += c0 * v0.x + c1 * v1.x;
                    a4.y += c0 * v0.y + c1 * v1.y;
                    a4.z += c0 * v0.z + c1 * v1.z;
                    a4.w += c0 * v0.w + c1 * v1.w;
                }
                if (e < e1) {
                    int   s0 = g_bsrc[e];
                    float c0 = g_bcoef[e];
                    float4 v0 = *(const float4*)(xk + (size_t)s0 * FD);
                    a4.x += c0 * v0.x; a4.y += c0 * v0.y;
                    a4.z += c0 * v0.z; a4.w += c0 * v0.w;
                }
            }
            sA16[m][lane * 2 + 0] = pack_bf16(a4.x, a4.y);
            sA16[m][lane * 2 + 1] = pack_bf16(a4.z, a4.w);
        }

        // ---- full-K B fill: word (n, kp) = {lo=W[2kp][n], hi=W[2kp+1][n]}
#pragma unroll
        for (int it = 0; it < 8; it++) {
            int idx = tid + it * 256;        // 0..2047
            int kp  = idx & 63;
            int n4  = idx >> 6;
            float4 v0 = *(const float4*)(Wr + (size_t)(2 * kp)     * FD + n4 * 4);
            float4 v1 = *(const float4*)(Wr + (size_t)(2 * kp + 1) * FD + n4 * 4);
            sB16[n4 * 4 + 0][kp] = pack_bf16(v0.x, v1.x);
            sB16[n4 * 4 + 1][kp] = pack_bf16(v0.y, v1.y);
            sB16[n4 * 4 + 2][kp] = pack_bf16(v0.z, v1.z);
            sB16[n4 * 4 + 3][kp] = pack_bf16(v0.w, v1.w);
        }
        __syncthreads();

        // ---- 8 K-steps of m16n8k16; fragments via ldmatrix.x4
#pragma unroll
        for (int kw = 0; kw < 8; kw++) {
            const unsigned koff = kw * 32;   // 8 words = 32 bytes per k-step
            unsigned a[4][4], b[4][2];
#pragma unroll
            for (int mf = 0; mf < 4; mf++)
                ldsm_x4(a[mf][0], a[mf][1], a[mf][2], a[mf][3],
                        aBase + mf * aMfStride + koff);
            ldsm_x4(b[0][0], b[0][1], b[1][0], b[1][1], bBase + koff);
            ldsm_x4(b[2][0], b[2][1], b[3][0], b[3][1], bBase + bPairStride + koff);
#pragma unroll
            for (int mf = 0; mf < 4; mf++)
#pragma unroll
                for (int nf = 0; nf < 4; nf++)
                    mma_bf16(acc[mf][nf][0], acc[mf][nf][1], acc[mf][nf][2], acc[mf][nf][3],
                             a[mf][0], a[mf][1], a[mf][2], a[mf][3],
                             b[nf][0], b[nf][1]);
        }
    }

    // ---- epilogue: bias + ReLU, single write of H1 (C layout unchanged)
#pragma unroll
    for (int mf = 0; mf < 4; mf++) {
        int row_a = row0 + mbase + mf * 16 + gq;
        int row_b = row_a + 8;
#pragma unroll
        for (int nf = 0; nf < 4; nf++) {
            int col = nbase + nf * 8 + 2 * tq;
            if (row_a < NN) {
                float2 o = make_float2(acc[mf][nf][0], acc[mf][nf][1]);
                o.x = fmaxf(o.x + sbias[col],     0.f);
                o.y = fmaxf(o.y + sbias[col + 1], 0.f);
                *(float2*)(g_H1 + (size_t)row_a * FD + col) = o;
            }
            if (row_b < NN) {
                float2 o = make_float2(acc[mf][nf][2], acc[mf][nf][3]);
                o.x = fmaxf(o.x + sbias[col],     0.f);
                o.y = fmaxf(o.y + sbias[col + 1], 0.f);
                *(float2*)(g_H1 + (size_t)row_b * FD + col) = o;
            }
        }
    }
}

// ---------------- layer-2: s2[r][j] = sum_n w[r,n] * H1[n][j] ----------------
#define L2CH 512
__global__ __launch_bounds__(128)
void l2_kernel() {
    __shared__ float sw[RR][L2CH];
    int j  = threadIdx.x;
    int n0 = blockIdx.x * L2CH;
    int lim = NN - n0; if (lim > L2CH) lim = L2CH;

    for (int r = 0; r < RR; r++)
        for (int k = j; k < L2CH; k += 128)
            sw[r][k] = (k < lim) ? g_w[r * NN + n0 + k] : 0.f;
    __syncthreads();

    float acc[RR];
#pragma unroll
    for (int r = 0; r < RR; r++) acc[r] = 0.f;

    for (int k = 0; k < lim; k++) {
        float h = g_H1[(size_t)(n0 + k) * FD + j];
#pragma unroll
        for (int r = 0; r < RR; r++) acc[r] += sw[r][k] * h;
    }
#pragma unroll
    for (int r = 0; r < RR; r++)
        if (acc[r] != 0.f) atomicAdd(&g_s2[r * FD + j], acc[r]);
}

// ---------------- head: pool = sum_r s2[r] @ W2_r; classifier ----------------
__global__ void head_kernel(float* out) {
    __shared__ float s0[FD], s1[FD], sa[FD];
    int j = threadIdx.x;
    float pool = 0.f;
#pragma unroll
    for (int r = 0; r < RR; r++) {
        const float* s2r = g_s2 + r * FD;
        const float* W2r = g_W2 + (size_t)r * FD * FD;
        float a = 0.f;
        for (int k = 0; k < FD; k++) a += s2r[k] * W2r[k * FD + j];
        pool += a;
    }
    float bs = 0.f;
#pragma unroll
    for (int r = 0; r < RR; r++) bs += g_b2[r * FD + j];
    float v = pool * (1.0f / (float)NN) + bs;
    s0[j] = v * g_Wc[j * 2 + 0];
    s1[j] = v * g_Wc[j * 2 + 1];
    sa[j] = fabsf(pool);
    __syncthreads();
    for (int s = 64; s > 0; s >>= 1) {
        if (j < s) { s0[j] += s0[j + s]; s1[j] += s1[j + s]; sa[j] += sa[j + s]; }
        __syncthreads();
    }
    if (j == 0) {
        if (sa[0] == 0.f) {
            float code;
            if      (g_diagcode)    code = 3.0e12f;
            else if (g_cnt[0] == 0) code = 3.0e4f;
            else if (g_cnt[1] == 0) code = 3.0e6f;
            else                    code = 3.0e10f;
            out[0] = code + (float)g_e64;
            out[1] = -code;
        } else {
            out[0] = s0[0] + g_bc[0];
            out[1] = s1[0] + g_bc[1];
        }
    }
}

__global__ void diag_kernel(float* out, float a, float b) {
    out[0] = a;
    out[1] = b;
}

// ---------------- launch ------------------------------------------------------
extern "C" void kernel_launch(void* const* d_in, const int* in_sizes, int n_in,
                              void* d_out, int out_size) {
    float* out = (float*)d_out;

    if (n_in < 9) {
        diag_kernel<<<1, 1>>>(out, 3.0e14f, (float)n_in);
        return;
    }

    InArgs a;
    for (int i = 0; i < 9; i++) {
        a.p[i]  = d_in[i];
        a.sz[i] = (long long)in_sizes[i];
    }
    classify_kernel<<<1, 32>>>(a);

    zero_pre_kernel<<<512, 256>>>();
    degree_kernel<<<(RE + 255) / 256, 256>>>();
    norm_kernel<<<(RN + 255) / 256, 256>>>();

    scan1_kernel<<<NPART, 256>>>();
    scan2_kernel<<<1, 1024>>>();
    scan3_kernel<<<NPART, 256>>>();

    bin_kernel<<<(RE + 255) / 256, 256>>>();

    // layer 1, fully fused: full-K gather + 6 bf16 GEMMs (ldmatrix frags) + bias + ReLU
    fused_l1_kernel<<<(NN + 127) / 128, 256>>>();

    // layer 2 collapsed twice: s2[r] = sum_n w[r,n] H1[n]; pool = sum_r s2 @ W2_r
    l2_kernel<<<(NN + L2CH - 1) / L2CH, 128>>>();

    head_kernel<<<1, FD>>>(out);
}